// round 1
// baseline (speedup 1.0000x reference)
#include <cuda_runtime.h>
#include <math.h>

#define C_  32
#define D_  48
#define H_  128
#define W_  160
#define HW_ (H_*W_)
#define NV_ 4   // V-1 source views

// Scratch (device globals: allocation-free rule)
__device__ float g_rt[NV_][12];                 // per-view rot(9) + trans(3)
__device__ float g_vol[C_*D_*H_*W_];            // volume_mean, layout (c,d,y,x)
__device__ float g_cost[D_*H_*W_];              // conv output (d,y,x)

// ---------------------------------------------------------------------------
// K0: projection algebra. proj layout: (B=1, V=5, 2, 4, 4).
// ref_new = [K3*R_ref | K3*T_ref ; 0 0 0 1]; src_new analogous.
// proj_v = src_new * inv(ref_new):  rot = As*Ar^{-1}, trans = as - rot*ar.
// ---------------------------------------------------------------------------
__global__ void k_params(const float* __restrict__ proj) {
    if (threadIdx.x != 0 || blockIdx.x != 0) return;

    double Ar[9], ar[3];
    {
        const float* E = proj;        // view 0 extrinsic
        const float* K = proj + 16;   // view 0 intrinsic
        for (int i = 0; i < 3; i++) {
            for (int j = 0; j < 3; j++) {
                double s = 0.0;
                for (int k = 0; k < 3; k++) s += (double)K[i*4+k] * (double)E[k*4+j];
                Ar[i*3+j] = s;
            }
            double s = 0.0;
            for (int k = 0; k < 3; k++) s += (double)K[i*4+k] * (double)E[k*4+3];
            ar[i] = s;
        }
    }
    // 3x3 inverse (adjugate), fp64
    double inv[9];
    double det = Ar[0]*(Ar[4]*Ar[8]-Ar[5]*Ar[7])
               - Ar[1]*(Ar[3]*Ar[8]-Ar[5]*Ar[6])
               + Ar[2]*(Ar[3]*Ar[7]-Ar[4]*Ar[6]);
    double id = 1.0 / det;
    inv[0] = (Ar[4]*Ar[8]-Ar[5]*Ar[7])*id;
    inv[1] = (Ar[2]*Ar[7]-Ar[1]*Ar[8])*id;
    inv[2] = (Ar[1]*Ar[5]-Ar[2]*Ar[4])*id;
    inv[3] = (Ar[5]*Ar[6]-Ar[3]*Ar[8])*id;
    inv[4] = (Ar[0]*Ar[8]-Ar[2]*Ar[6])*id;
    inv[5] = (Ar[2]*Ar[3]-Ar[0]*Ar[5])*id;
    inv[6] = (Ar[3]*Ar[7]-Ar[4]*Ar[6])*id;
    inv[7] = (Ar[1]*Ar[6]-Ar[0]*Ar[7])*id;
    inv[8] = (Ar[0]*Ar[4]-Ar[1]*Ar[3])*id;

    for (int v = 0; v < NV_; v++) {
        const float* E = proj + (v+1)*32;
        const float* K = proj + (v+1)*32 + 16;
        double As[9], as_[3];
        for (int i = 0; i < 3; i++) {
            for (int j = 0; j < 3; j++) {
                double s = 0.0;
                for (int k = 0; k < 3; k++) s += (double)K[i*4+k] * (double)E[k*4+j];
                As[i*3+j] = s;
            }
            double s = 0.0;
            for (int k = 0; k < 3; k++) s += (double)K[i*4+k] * (double)E[k*4+3];
            as_[i] = s;
        }
        double rot[9], tr[3];
        for (int i = 0; i < 3; i++)
            for (int j = 0; j < 3; j++) {
                double s = 0.0;
                for (int k = 0; k < 3; k++) s += As[i*3+k] * inv[k*3+j];
                rot[i*3+j] = s;
            }
        for (int i = 0; i < 3; i++) {
            double s = as_[i];
            for (int k = 0; k < 3; k++) s -= rot[i*3+k] * ar[k];
            tr[i] = s;
        }
        for (int i = 0; i < 9; i++) g_rt[v][i] = (float)rot[i];
        for (int i = 0; i < 3; i++) g_rt[v][9+i] = (float)tr[i];
    }
}

// ---------------------------------------------------------------------------
// K1: build volume_mean (c,d,y,x). One block per (y,d); thread = x.
// Bilinear taps precomputed per view (shared across 32 channels).
// ---------------------------------------------------------------------------
__global__ void __launch_bounds__(W_) k_vol(const float* __restrict__ src,
                                            const float* __restrict__ ref,
                                            const float* __restrict__ depv) {
    const int x = threadIdx.x;
    const int y = blockIdx.x;
    const int d = blockIdx.y;
    const float dep = depv[d];

    int   off[NV_][4];
    float wgt[NV_][4];

#pragma unroll
    for (int v = 0; v < NV_; v++) {
        const float* rt = g_rt[v];
        float fx = (float)x, fy = (float)y;
        float rx = rt[0]*fx + rt[1]*fy + rt[2];
        float ry = rt[3]*fx + rt[4]*fy + rt[5];
        float rz = rt[6]*fx + rt[7]*fy + rt[8];
        float pz = rz*dep + rt[11];
        float px = (rx*dep + rt[9])  / pz;
        float py = (ry*dep + rt[10]) / pz;

        float x0f = floorf(px), y0f = floorf(py);
        float wx = px - x0f,    wy = py - y0f;

        bool vx0 = (x0f >=  0.f) && (x0f <= (float)(W_-1));
        bool vx1 = (x0f >= -1.f) && (x0f <= (float)(W_-2));
        bool vy0 = (y0f >=  0.f) && (y0f <= (float)(H_-1));
        bool vy1 = (y0f >= -1.f) && (y0f <= (float)(H_-2));

        int ix0 = min(max((int)x0f,     0), W_-1);
        int ix1 = min(max((int)x0f + 1, 0), W_-1);
        int iy0 = min(max((int)y0f,     0), H_-1);
        int iy1 = min(max((int)y0f + 1, 0), H_-1);

        wgt[v][0] = (vx0 && vy0) ? (1.f-wx)*(1.f-wy) : 0.f;
        wgt[v][1] = (vx1 && vy0) ? wx*(1.f-wy)       : 0.f;
        wgt[v][2] = (vx0 && vy1) ? (1.f-wx)*wy       : 0.f;
        wgt[v][3] = (vx1 && vy1) ? wx*wy             : 0.f;

        off[v][0] = iy0*W_ + ix0;
        off[v][1] = iy0*W_ + ix1;
        off[v][2] = iy1*W_ + ix0;
        off[v][3] = iy1*W_ + ix1;
    }

    const int pix = y*W_ + x;
#pragma unroll 4
    for (int c = 0; c < C_; c++) {
        float acc = 0.f;
#pragma unroll
        for (int v = 0; v < NV_; v++) {
            const float* S = src + (size_t)(v*C_ + c) * HW_;
            float s = wgt[v][0] * __ldg(&S[off[v][0]])
                    + wgt[v][1] * __ldg(&S[off[v][1]])
                    + wgt[v][2] * __ldg(&S[off[v][2]])
                    + wgt[v][3] * __ldg(&S[off[v][3]]);
            acc += ref[(size_t)(v*C_ + c) * HW_ + pix] * s;
        }
        g_vol[(((size_t)c*D_ + d)*H_ + y)*W_ + x] = acc * 0.25f;
    }
}

// ---------------------------------------------------------------------------
// K2: 3x3x3 conv (cross-correlation), 32ch -> 1, SAME zero-pad.
// Block tile: 8 d x 8 y x 32 x outputs; per-channel smem tile 10x10x34.
// Thread owns 8 d-outputs (register sliding window along d).
// ---------------------------------------------------------------------------
__global__ void __launch_bounds__(256) k_conv(const float* __restrict__ wreg) {
    __shared__ float tile[10*10*34];
    __shared__ float wsh[C_*27];

    const int tx = threadIdx.x, ty = threadIdx.y;
    const int tid = ty*32 + tx;
    const int x0 = blockIdx.x*32, y0 = blockIdx.y*8, d0 = blockIdx.z*8;

    for (int i = tid; i < C_*27; i += 256) wsh[i] = wreg[i];

    float acc[8];
#pragma unroll
    for (int j = 0; j < 8; j++) acc[j] = 0.f;

    for (int c = 0; c < C_; c++) {
        __syncthreads();
        for (int i = tid; i < 10*10*34; i += 256) {
            int dd = i / 340;
            int r  = i - dd*340;
            int yy = r / 34;
            int xx = r - yy*34;
            int gd = d0 - 1 + dd, gy = y0 - 1 + yy, gx = x0 - 1 + xx;
            float v = 0.f;
            if (gd >= 0 && gd < D_ && gy >= 0 && gy < H_ && gx >= 0 && gx < W_)
                v = g_vol[(((size_t)c*D_ + gd)*H_ + gy)*W_ + gx];
            tile[i] = v;
        }
        __syncthreads();

#pragma unroll
        for (int dy = 0; dy < 3; dy++)
#pragma unroll
        for (int dx = 0; dx < 3; dx++) {
            float col[10];
#pragma unroll
            for (int k = 0; k < 10; k++)
                col[k] = tile[(k*10 + ty + dy)*34 + tx + dx];
#pragma unroll
            for (int dz = 0; dz < 3; dz++) {
                float wv = wsh[c*27 + dz*9 + dy*3 + dx];
#pragma unroll
                for (int j = 0; j < 8; j++)
                    acc[j] += wv * col[j + dz];
            }
        }
    }

#pragma unroll
    for (int j = 0; j < 8; j++)
        g_cost[(size_t)(d0 + j)*HW_ + (y0 + ty)*W_ + (x0 + tx)] = acc[j];
}

// ---------------------------------------------------------------------------
// K3: softmax over D + expected depth + confidence (window of 4 at trunc idx).
// ---------------------------------------------------------------------------
__global__ void __launch_bounds__(W_) k_post(const float* __restrict__ depv,
                                             float* __restrict__ out) {
    const int x = threadIdx.x;
    const int y = blockIdx.x;
    const int pix = y*W_ + x;

    float m = -1e30f;
    for (int d = 0; d < D_; d++)
        m = fmaxf(m, g_cost[(size_t)d*HW_ + pix]);

    float s = 0.f, sd = 0.f, sdep = 0.f;
    for (int d = 0; d < D_; d++) {
        float e = expf(g_cost[(size_t)d*HW_ + pix] - m);
        s    += e;
        sd   += e * (float)d;
        sdep += e * depv[d];
    }
    float invs = 1.f / s;
    out[pix] = sdep * invs;

    int idx = (int)(sd * invs);          // truncation, matches astype(int32)
    idx = min(max(idx, 0), D_-1);

    float cw = 0.f;
#pragma unroll
    for (int t = -1; t <= 2; t++) {
        int dd = idx + t;
        if (dd >= 0 && dd < D_)
            cw += expf(g_cost[(size_t)dd*HW_ + pix] - m);
    }
    out[HW_ + pix] = cw * invs;
}

// ---------------------------------------------------------------------------
extern "C" void kernel_launch(void* const* d_in, const int* in_sizes, int n_in,
                              void* d_out, int out_size) {
    const float* ref  = (const float*)d_in[0];
    const float* src  = (const float*)d_in[1];
    const float* proj = (const float*)d_in[2];
    const float* depv = (const float*)d_in[3];

    // locate w_reg by element count (num_depth may or may not be a device input)
    const float* wreg = (const float*)d_in[n_in - 1];
    for (int i = 4; i < n_in; i++)
        if (in_sizes[i] == C_*27) { wreg = (const float*)d_in[i]; break; }

    float* out = (float*)d_out;

    k_params<<<1, 32>>>(proj);
    k_vol<<<dim3(H_, D_), W_>>>(src, ref, depv);
    k_conv<<<dim3(W_/32, H_/8, D_/8), dim3(32, 8)>>>(wreg);
    k_post<<<H_, W_>>>(depv, out);
}

// round 3
// speedup vs baseline: 1.0064x; 1.0064x over previous
#include <cuda_runtime.h>
#include <math.h>

#define C_  32
#define C2_ 16
#define D_  48
#define H_  128
#define W_  160
#define HW_ (H_*W_)
#define NV_ 4   // V-1 source views

// Scratch (device globals: allocation-free rule)
__device__ float  g_rt[NV_][12];                // per-view rot(9) + trans(3)
__device__ float2 g_src2[NV_*C2_*HW_];          // src feats, channel-paired fp32
__device__ float2 g_ref2[NV_*C2_*HW_];          // ref feats, channel-paired fp32
__device__ float2 g_vol2[C2_*D_*HW_];           // volume_mean, (c2,d,y,x) float2
__device__ float  g_cost[D_*HW_];               // conv output (d,y,x)

// ---------------------------------------------------------------------------
// K0: projection algebra (fp64). proj layout: (B=1, V=5, 2, 4, 4).
// ---------------------------------------------------------------------------
__global__ void k_params(const float* __restrict__ proj) {
    if (threadIdx.x != 0 || blockIdx.x != 0) return;

    double Ar[9], ar[3];
    {
        const float* E = proj;
        const float* K = proj + 16;
        for (int i = 0; i < 3; i++) {
            for (int j = 0; j < 3; j++) {
                double s = 0.0;
                for (int k = 0; k < 3; k++) s += (double)K[i*4+k] * (double)E[k*4+j];
                Ar[i*3+j] = s;
            }
            double s = 0.0;
            for (int k = 0; k < 3; k++) s += (double)K[i*4+k] * (double)E[k*4+3];
            ar[i] = s;
        }
    }
    double inv[9];
    double det = Ar[0]*(Ar[4]*Ar[8]-Ar[5]*Ar[7])
               - Ar[1]*(Ar[3]*Ar[8]-Ar[5]*Ar[6])
               + Ar[2]*(Ar[3]*Ar[7]-Ar[4]*Ar[6]);
    double id = 1.0 / det;
    inv[0] = (Ar[4]*Ar[8]-Ar[5]*Ar[7])*id;
    inv[1] = (Ar[2]*Ar[7]-Ar[1]*Ar[8])*id;
    inv[2] = (Ar[1]*Ar[5]-Ar[2]*Ar[4])*id;
    inv[3] = (Ar[5]*Ar[6]-Ar[3]*Ar[8])*id;
    inv[4] = (Ar[0]*Ar[8]-Ar[2]*Ar[6])*id;
    inv[5] = (Ar[2]*Ar[3]-Ar[0]*Ar[5])*id;
    inv[6] = (Ar[3]*Ar[7]-Ar[4]*Ar[6])*id;
    inv[7] = (Ar[1]*Ar[6]-Ar[0]*Ar[7])*id;
    inv[8] = (Ar[0]*Ar[4]-Ar[1]*Ar[3])*id;

    for (int v = 0; v < NV_; v++) {
        const float* E = proj + (v+1)*32;
        const float* K = proj + (v+1)*32 + 16;
        double As[9], as_[3];
        for (int i = 0; i < 3; i++) {
            for (int j = 0; j < 3; j++) {
                double s = 0.0;
                for (int k = 0; k < 3; k++) s += (double)K[i*4+k] * (double)E[k*4+j];
                As[i*3+j] = s;
            }
            double s = 0.0;
            for (int k = 0; k < 3; k++) s += (double)K[i*4+k] * (double)E[k*4+3];
            as_[i] = s;
        }
        double rot[9], tr[3];
        for (int i = 0; i < 3; i++)
            for (int j = 0; j < 3; j++) {
                double s = 0.0;
                for (int k = 0; k < 3; k++) s += As[i*3+k] * inv[k*3+j];
                rot[i*3+j] = s;
            }
        for (int i = 0; i < 3; i++) {
            double s = as_[i];
            for (int k = 0; k < 3; k++) s -= rot[i*3+k] * ar[k];
            tr[i] = s;
        }
        for (int i = 0; i < 9; i++) g_rt[v][i] = (float)rot[i];
        for (int i = 0; i < 3; i++) g_rt[v][9+i] = (float)tr[i];
    }
}

// ---------------------------------------------------------------------------
// Kc: (V,C,H,W) fp32 -> channel-paired (V,C/2,H,W) float2. Exact permutation.
// ---------------------------------------------------------------------------
__global__ void __launch_bounds__(256) k_cvt(const float* __restrict__ src,
                                             const float* __restrict__ ref) {
    int idx = blockIdx.x * 256 + threadIdx.x;
    if (idx >= NV_*C2_*HW_) return;
    int p   = idx % HW_;
    int vc2 = idx / HW_;
    int v   = vc2 >> 4;
    int c2  = vc2 & 15;
    size_t a = (size_t)(v*C_ + 2*c2) * HW_ + p;
    g_src2[idx] = make_float2(src[a], src[a + HW_]);
    g_ref2[idx] = make_float2(ref[a], ref[a + HW_]);
}

// ---------------------------------------------------------------------------
// K1: build volume_mean. Block = 32 x-pixels x 1 y x all 48 d.
// Threads (32,8); thread handles 6 consecutive d. ref staged in smem (once
// per pixel, not once per (pixel,d)). Gathers are float2 (2 channels / load).
// ---------------------------------------------------------------------------
__global__ void __launch_bounds__(256) k_vol(const float* __restrict__ depv) {
    __shared__ float2 refs[NV_][C2_][32];

    const int tx = threadIdx.x;            // x within tile
    const int dg = threadIdx.y;            // d group
    const int tid = dg*32 + tx;
    const int x0 = blockIdx.x * 32;
    const int y  = blockIdx.y;
    const int x  = x0 + tx;
    const int pix = y*W_ + x;

    // stage ref float2 tile: [4 views][16 c2][32 x]
    for (int i = tid; i < NV_*C2_*32; i += 256) {
        int v  = i >> 9;
        int r  = i & 511;
        int c2 = r >> 5;
        int xx = r & 31;
        refs[v][c2][xx] = g_ref2[(v*C2_ + c2)*HW_ + y*W_ + x0 + xx];
    }
    __syncthreads();

    const float fx = (float)x, fy = (float)y;

    for (int i = 0; i < 6; i++) {
        const int d = dg*6 + i;
        const float dep = depv[d];

        int   off[NV_][4];
        float wgt[NV_][4];
#pragma unroll
        for (int v = 0; v < NV_; v++) {
            const float* rt = g_rt[v];
            float rx = rt[0]*fx + rt[1]*fy + rt[2];
            float ry = rt[3]*fx + rt[4]*fy + rt[5];
            float rz = rt[6]*fx + rt[7]*fy + rt[8];
            float pz = rz*dep + rt[11];
            float px = (rx*dep + rt[9])  / pz;
            float py = (ry*dep + rt[10]) / pz;

            float x0f = floorf(px), y0f = floorf(py);
            float wx = px - x0f,    wy = py - y0f;

            bool vx0 = (x0f >=  0.f) && (x0f <= (float)(W_-1));
            bool vx1 = (x0f >= -1.f) && (x0f <= (float)(W_-2));
            bool vy0 = (y0f >=  0.f) && (y0f <= (float)(H_-1));
            bool vy1 = (y0f >= -1.f) && (y0f <= (float)(H_-2));

            int ix0 = min(max((int)x0f,     0), W_-1);
            int ix1 = min(max((int)x0f + 1, 0), W_-1);
            int iy0 = min(max((int)y0f,     0), H_-1);
            int iy1 = min(max((int)y0f + 1, 0), H_-1);

            wgt[v][0] = (vx0 && vy0) ? (1.f-wx)*(1.f-wy) : 0.f;
            wgt[v][1] = (vx1 && vy0) ? wx*(1.f-wy)       : 0.f;
            wgt[v][2] = (vx0 && vy1) ? (1.f-wx)*wy       : 0.f;
            wgt[v][3] = (vx1 && vy1) ? wx*wy             : 0.f;

            off[v][0] = iy0*W_ + ix0;
            off[v][1] = iy0*W_ + ix1;
            off[v][2] = iy1*W_ + ix0;
            off[v][3] = iy1*W_ + ix1;
        }

#pragma unroll 4
        for (int c2 = 0; c2 < C2_; c2++) {
            float ax = 0.f, ay = 0.f;
#pragma unroll
            for (int v = 0; v < NV_; v++) {
                const float2* S = g_src2 + (size_t)(v*C2_ + c2) * HW_;
                float2 t0 = __ldg(&S[off[v][0]]);
                float2 t1 = __ldg(&S[off[v][1]]);
                float2 t2 = __ldg(&S[off[v][2]]);
                float2 t3 = __ldg(&S[off[v][3]]);
                float sx = wgt[v][0]*t0.x + wgt[v][1]*t1.x + wgt[v][2]*t2.x + wgt[v][3]*t3.x;
                float sy = wgt[v][0]*t0.y + wgt[v][1]*t1.y + wgt[v][2]*t2.y + wgt[v][3]*t3.y;
                float2 r = refs[v][c2][tx];
                ax += r.x * sx;
                ay += r.y * sy;
            }
            g_vol2[((size_t)c2*D_ + d)*HW_ + pix] = make_float2(ax*0.25f, ay*0.25f);
        }
    }
}

// ---------------------------------------------------------------------------
// K2: 3x3x3 conv (cross-correlation), 32ch -> 1, SAME zero-pad.
// Channel-pair float2 tiles: 16 c2 iterations, smem tile 10x10x34 float2.
// Thread owns 8 d-outputs (register sliding window along d).
// ---------------------------------------------------------------------------
__global__ void __launch_bounds__(256) k_conv(const float* __restrict__ wreg) {
    __shared__ float2 tile[10*10*34];
    __shared__ float  wsh[C_*27];

    const int tx = threadIdx.x, ty = threadIdx.y;
    const int tid = ty*32 + tx;
    const int x0 = blockIdx.x*32, y0 = blockIdx.y*8, d0 = blockIdx.z*8;

    for (int i = tid; i < C_*27; i += 256) wsh[i] = wreg[i];

    float acc[8];
#pragma unroll
    for (int j = 0; j < 8; j++) acc[j] = 0.f;

    for (int c2 = 0; c2 < C2_; c2++) {
        __syncthreads();
        for (int i = tid; i < 10*10*34; i += 256) {
            int dd = i / 340;
            int r  = i - dd*340;
            int yy = r / 34;
            int xx = r - yy*34;
            int gd = d0 - 1 + dd, gy = y0 - 1 + yy, gx = x0 - 1 + xx;
            float2 v = make_float2(0.f, 0.f);
            if (gd >= 0 && gd < D_ && gy >= 0 && gy < H_ && gx >= 0 && gx < W_)
                v = g_vol2[((size_t)c2*D_ + gd)*HW_ + gy*W_ + gx];
            tile[i] = v;
        }
        __syncthreads();

#pragma unroll
        for (int dy = 0; dy < 3; dy++)
#pragma unroll
        for (int dx = 0; dx < 3; dx++) {
            float2 col[10];
#pragma unroll
            for (int k = 0; k < 10; k++)
                col[k] = tile[(k*10 + ty + dy)*34 + tx + dx];
#pragma unroll
            for (int dz = 0; dz < 3; dz++) {
                float wa = wsh[(2*c2  )*27 + dz*9 + dy*3 + dx];
                float wb = wsh[(2*c2+1)*27 + dz*9 + dy*3 + dx];
#pragma unroll
                for (int j = 0; j < 8; j++)
                    acc[j] += wa*col[j + dz].x + wb*col[j + dz].y;
            }
        }
    }

#pragma unroll
    for (int j = 0; j < 8; j++)
        g_cost[(size_t)(d0 + j)*HW_ + (y0 + ty)*W_ + (x0 + tx)] = acc[j];
}

// ---------------------------------------------------------------------------
// K3: softmax over D + expected depth + confidence. Cost cached in registers.
// ---------------------------------------------------------------------------
__global__ void __launch_bounds__(W_) k_post(const float* __restrict__ depv,
                                             float* __restrict__ out) {
    const int x = threadIdx.x;
    const int y = blockIdx.x;
    const int pix = y*W_ + x;

    float cv[D_];
    float m = -1e30f;
#pragma unroll
    for (int d = 0; d < D_; d++) {
        cv[d] = g_cost[(size_t)d*HW_ + pix];
        m = fmaxf(m, cv[d]);
    }

    float s = 0.f, sd = 0.f, sdep = 0.f;
#pragma unroll
    for (int d = 0; d < D_; d++) {
        float e = expf(cv[d] - m);
        s    += e;
        sd   += e * (float)d;
        sdep += e * depv[d];
    }
    float invs = 1.f / s;
    out[pix] = sdep * invs;

    int idx = (int)(sd * invs);          // truncation, matches astype(int32)
    idx = min(max(idx, 0), D_-1);

    float cw = 0.f;
#pragma unroll
    for (int t = -1; t <= 2; t++) {
        int dd = idx + t;
        if (dd >= 0 && dd < D_)
            cw += expf(cv[dd] - m);
    }
    out[HW_ + pix] = cw * invs;
}

// ---------------------------------------------------------------------------
extern "C" void kernel_launch(void* const* d_in, const int* in_sizes, int n_in,
                              void* d_out, int out_size) {
    const float* ref  = (const float*)d_in[0];
    const float* src  = (const float*)d_in[1];
    const float* proj = (const float*)d_in[2];
    const float* depv = (const float*)d_in[3];

    const float* wreg = (const float*)d_in[n_in - 1];
    for (int i = 4; i < n_in; i++)
        if (in_sizes[i] == C_*27) { wreg = (const float*)d_in[i]; break; }

    float* out = (float*)d_out;

    k_params<<<1, 32>>>(proj);
    k_cvt<<<(NV_*C2_*HW_ + 255)/256, 256>>>(src, ref);
    k_vol<<<dim3(W_/32, H_), dim3(32, 8)>>>(depv);
    k_conv<<<dim3(W_/32, H_/8, D_/8), dim3(32, 8)>>>(wreg);
    k_post<<<H_, W_>>>(depv, out);
}